// round 12
// baseline (speedup 1.0000x reference)
#include <cuda_runtime.h>
#include <math.h>
#include <float.h>

#define NC   4096
#define NP   32
#define KNB  8
#define C1   64
#define C2   128
#define S1   68
#define S2   132
#define ECH  384
#define NGRP 3
#define NTH  (NGRP * 256)
#define NBLK 152      // persistent: one block per SM

typedef unsigned long long ull;

// ---- shared (block-common) smem layout, float words ----
#define OFF_W2    0                          // 16384
#define OFF_W1    (OFF_W2 + 16384)           // 384
#define OFF_B1    (OFF_W1 + 384)
#define OFF_G1    (OFF_B1 + 64)
#define OFF_BE1   (OFF_G1 + 64)
#define OFF_B2    (OFF_BE1 + 64)
#define OFF_G2    (OFF_B2 + 128)
#define OFF_BE2   (OFF_G2 + 128)
#define OFF_FLAGS (OFF_BE2 + 128)            // 6 int flags (any g<=0 per loader warp)
#define SHARED_WORDS (OFF_FLAGS + 8)

// ---- per-group smem layout ----
#define GP_P1   0
#define GP_Q1   2176
#define GP_P2   0
#define GP_Q2   4224
#define GP_FB   8448                        // F1 during GEMM; warpbuf during edge2
#define GP_XS   (GP_FB + 2176)              // 96: x; also sumV table inside edge phases
#define GP_IDX  (GP_XS + 96)                // 256 ints
#define GP_TK   (GP_IDX + 256)              // 1 word: ticket broadcast
#define GRP_WORDS (GP_TK + 8)

#define SMEM1_WORDS (SHARED_WORDS + NGRP * GRP_WORDS)
#define SMEM1_BYTES (SMEM1_WORDS * 4)

#define SMEM2_BYTES ((64*128 + 128*64) * 4)

__device__ float g_pool[NC * C2];
__device__ unsigned g_ticket;

// ---- packed f32x2 helpers ----
__device__ __forceinline__ ull pk2(float lo, float hi) {
    ull r; asm("mov.b64 %0, {%1, %2};" : "=l"(r) : "f"(lo), "f"(hi)); return r;
}
__device__ __forceinline__ void upk2(ull v, float& lo, float& hi) {
    asm("mov.b64 {%0, %1}, %2;" : "=f"(lo), "=f"(hi) : "l"(v));
}
__device__ __forceinline__ ull fma2(ull a, ull b, ull c) {
    ull d; asm("fma.rn.f32x2 %0, %1, %2, %3;" : "=l"(d) : "l"(a), "l"(b), "l"(c)); return d;
}
__device__ __forceinline__ ull add2(ull a, ull b) {
    ull d; asm("add.rn.f32x2 %0, %1, %2;" : "=l"(d) : "l"(a), "l"(b)); return d;
}

__device__ __forceinline__ float elu_f(float x) {
    return x > 0.f ? x : (__expf(x) - 1.f);
}

__device__ __forceinline__ void group_bar(int gid) {
    asm volatile("bar.sync %0, %1;" :: "r"(gid + 1), "r"(256) : "memory");
}

// Edge phase, mu-trick + zmax-only + uniform npass cold path.
// Thread (i,s) owns NCHUNK float4 chunks: channels {s*4 + j*32 + l}.
// Chunk offsets s*4 mod 32 are distinct across the octet -> conflict-free LDS.
template<int NCHUNK, int STRIDE>
__device__ __forceinline__ void edge_phase_fast(
    const float* __restrict__ U, const float* __restrict__ V,
    float* __restrict__ sumVsm, const int* __restrict__ idxs,
    const float* __restrict__ gvec, const float* __restrict__ bevec,
    float invC, int i, int s, int gid, int npass, float* __restrict__ o)
{
    constexpr int P = 2 * NCHUNK;            // ull pairs
    const int base = s * 4;
    ull u[P];
    {
#pragma unroll
        for (int j = 0; j < NCHUNK; j++) {
            const ulonglong2 t = *reinterpret_cast<const ulonglong2*>(U + i * STRIDE + base + j * 32);
            u[2*j] = t.x; u[2*j+1] = t.y;
        }
    }
    float sumU, sumV;
    {
        ull su = 0ULL;
#pragma unroll
        for (int p = 0; p < P; p++) su = add2(su, u[p]);
        float a, b; upk2(su, a, b); sumU = a + b;

        ull sv = 0ULL;
#pragma unroll
        for (int j = 0; j < NCHUNK; j++) {
            const ulonglong2 t = *reinterpret_cast<const ulonglong2*>(V + i * STRIDE + base + j * 32);
            sv = add2(sv, t.x); sv = add2(sv, t.y);
        }
        upk2(sv, a, b); sumV = a + b;
    }
#pragma unroll
    for (int off = 1; off < 8; off <<= 1) {
        sumU += __shfl_xor_sync(0xffffffffu, sumU, off);
        sumV += __shfl_xor_sync(0xffffffffu, sumV, off);
    }
    if (s == 0) sumVsm[i] = sumV;
    group_bar(gid);

    float sgn = 1.f;
#pragma unroll 1
    for (int pass = 0; pass < npass; pass++, sgn = -1.f) {
        float zx[4 * NCHUNK];
#pragma unroll
        for (int c = 0; c < 4 * NCHUNK; c++) zx[c] = -FLT_MAX;

#pragma unroll
        for (int k = 0; k < KNB; k++) {
            const int n = idxs[i * KNB + k];
            const float mu = (sumU + sumVsm[n]) * invC;
            ull t[P];
            ull ss2 = 0ULL;
#pragma unroll
            for (int j = 0; j < NCHUNK; j++) {
                const ulonglong2 vv = *reinterpret_cast<const ulonglong2*>(V + n * STRIDE + base + j * 32);
                const ull t0 = add2(u[2*j],   vv.x);
                const ull t1 = add2(u[2*j+1], vv.y);
                t[2*j] = t0; t[2*j+1] = t1;
                ss2 = fma2(t0, t0, ss2); ss2 = fma2(t1, t1, ss2);
            }
            float ql, qh; upk2(ss2, ql, qh);
            float ss = ql + qh;
#pragma unroll
            for (int off = 1; off < 8; off <<= 1)
                ss += __shfl_xor_sync(0xffffffffu, ss, off);
            const float var = fmaxf(fmaf(-mu, mu, ss * invC), 0.f);
            const float rstd = rsqrtf(var + 1e-5f) * sgn;
            const ull rr = pk2(rstd, rstd);
            const float nm = -mu * rstd;
            const ull nn = pk2(nm, nm);
#pragma unroll
            for (int p = 0; p < P; p++) {
                const ull z2 = fma2(t[p], rr, nn);
                float zl, zh; upk2(z2, zl, zh);
                zx[2*p]   = fmaxf(zx[2*p],   zl);
                zx[2*p+1] = fmaxf(zx[2*p+1], zh);
            }
        }
#pragma unroll
        for (int j = 0; j < NCHUNK; j++) {
#pragma unroll
            for (int l = 0; l < 4; l++) {
                const int c = 4*j + l;
                const int ch = base + j * 32 + l;
                const float gv = gvec[ch];
                const bool take = (pass == 0) ? (gv > 0.f) : (gv <= 0.f);
                if (take) {
                    const float zz = (pass == 0) ? zx[c] : -zx[c];
                    o[c] = elu_f(fmaf(gv, zz, bevec[ch]));
                }
            }
        }
    }
}

__global__ __launch_bounds__(NTH, 1)
void knn_encoder_kernel(
    const float* __restrict__ x,
    const float* __restrict__ W1, const float* __restrict__ b1,
    const float* __restrict__ g1, const float* __restrict__ be1,
    const float* __restrict__ W2, const float* __restrict__ b2,
    const float* __restrict__ g2, const float* __restrict__ be2)
{
    extern __shared__ float sm[];
    const int tid = threadIdx.x;
    const int gid = tid >> 8;
    const int ltid = tid & 255;

    float* gp = sm + SHARED_WORDS + gid * GRP_WORDS;
    int* idxs = reinterpret_cast<int*>(gp + GP_IDX);
    unsigned* tk = reinterpret_cast<unsigned*>(gp + GP_TK);
    int* flags = reinterpret_cast<int*>(sm + OFF_FLAGS);

    // ---- block-common params (once per persistent block) ----
    if (tid < 384) sm[OFF_W1 + tid] = W1[tid];
    if (tid >= 384 && tid < 448) {
        int j = tid - 384;
        float gv = g1[j];
        sm[OFF_B1 + j] = b1[j]; sm[OFF_G1 + j] = gv; sm[OFF_BE1 + j] = be1[j];
        int any = __any_sync(0xffffffffu, gv <= 0.f);
        if ((tid & 31) == 0) flags[(tid - 384) >> 5] = any;
    }
    if (tid >= 448 && tid < 576) {
        int j = tid - 448;
        float gv = g2[j];
        sm[OFF_B2 + j] = b2[j]; sm[OFF_G2 + j] = gv; sm[OFF_BE2 + j] = be2[j];
        int any = __any_sync(0xffffffffu, gv <= 0.f);
        if ((tid & 31) == 0) flags[2 + ((tid - 448) >> 5)] = any;
    }
    {
        const float4* src = reinterpret_cast<const float4*>(W2);
        float4* dst = reinterpret_cast<float4*>(sm + OFF_W2);
        for (int t = tid; t < 4096; t += NTH) dst[t] = src[t];
    }
    __syncthreads();

    const int npass1 = 1 + ((flags[0] | flags[1]) ? 1 : 0);
    const int npass2 = 1 + ((flags[2] | flags[3] | flags[4] | flags[5]) ? 1 : 0);

    // ---- per-group persistent loop over clouds (atomic tickets) ----
#pragma unroll 1
    for (;;) {
        if (ltid == 0) *tk = atomicAdd(&g_ticket, 1u);
        group_bar(gid);
        const unsigned cloud = *tk;
        if (cloud >= NC) break;

        if (ltid < 96) gp[GP_XS + ltid] = x[cloud * NP * 3 + ltid];
        group_bar(gid);

        // ---- KNN (warp 0: per-point insertion sort) || conv1 (warps 1-7) ----
        if (ltid < 32) {
            const int i = ltid;
            const float xi0 = gp[GP_XS + i * 3 + 0];
            const float xi1 = gp[GP_XS + i * 3 + 1];
            const float xi2 = gp[GP_XS + i * 3 + 2];
            const float si = xi0 * xi0 + xi1 * xi1 + xi2 * xi2;
            float d[8]; int id[8];
#pragma unroll
            for (int j = 0; j < 8; j++) { d[j] = FLT_MAX; id[j] = 32; }
#pragma unroll 4
            for (int m = 0; m < 32; m++) {
                const float xm0 = gp[GP_XS + m * 3 + 0];
                const float xm1 = gp[GP_XS + m * 3 + 1];
                const float xm2 = gp[GP_XS + m * 3 + 2];
                const float smq = xm0 * xm0 + xm1 * xm1 + xm2 * xm2;
                const float dot = xi0 * xm0 + xi1 * xm1 + xi2 * xm2;
                float nd = si + smq - 2.f * dot;
                int ni = m;
#pragma unroll
                for (int j = 0; j < 8; j++) {
                    const bool lt = nd < d[j];
                    const float td = d[j]; const int ti = id[j];
                    d[j]  = lt ? nd : td;  id[j] = lt ? ni : ti;
                    nd    = lt ? td : nd;  ni    = lt ? ti : ni;
                }
            }
#pragma unroll
            for (int j = 0; j < 8; j++) idxs[i * KNB + j] = id[j];
        } else {
            for (int o = ltid - 32; o < NP * C1; o += 224) {
                const int i = o >> 6, j = o & 63;
                const float x0 = gp[GP_XS + i * 3 + 0];
                const float x1 = gp[GP_XS + i * 3 + 1];
                const float x2 = gp[GP_XS + i * 3 + 2];
                float p = sm[OFF_B1 + j];
                p = fmaf(x0, sm[OFF_W1 + j], p);
                p = fmaf(x1, sm[OFF_W1 + 64 + j], p);
                p = fmaf(x2, sm[OFF_W1 + 128 + j], p);
                float q = x0 * sm[OFF_W1 + 192 + j];
                q = fmaf(x1, sm[OFF_W1 + 256 + j], q);
                q = fmaf(x2, sm[OFF_W1 + 320 + j], q);
                gp[GP_P1 + i * S1 + j] = p;
                gp[GP_Q1 + i * S1 + j] = q;
            }
        }
        group_bar(gid);

        // ---- edge phase 1 -> F1[32][64] (chunked channels, conflict-free) ----
        {
            const int i = ltid >> 3, s = ltid & 7;
            float o[8];
            edge_phase_fast<2, S1>(gp + GP_P1, gp + GP_Q1, gp + GP_XS, idxs,
                                   sm + OFF_G1, sm + OFF_BE1,
                                   1.f / 64.f, i, s, gid, npass1, o);
            float* F1 = gp + GP_FB;
            *reinterpret_cast<float4*>(F1 + i * S1 + s * 4)      = *reinterpret_cast<float4*>(o);
            *reinterpret_cast<float4*>(F1 + i * S1 + s * 4 + 32) = *reinterpret_cast<float4*>(o + 4);
        }
        group_bar(gid);

        // ---- conv2 P/Q GEMM (FFMA2, vectorized a-loads) ----
        {
            const int rg = ltid & 7;
            const int cg = ltid >> 3;
            const int j0 = (cg & 15) * 8;
            const bool isQ = (cg & 16) != 0;
            const float* Wb = sm + OFF_W2 + (isQ ? 64 * 128 : 0) + j0;
            const float* F1 = gp + GP_FB;
            ull acc[4][4];
#pragma unroll
            for (int r = 0; r < 4; r++)
#pragma unroll
                for (int p = 0; p < 4; p++) acc[r][p] = 0ULL;

#pragma unroll 4
            for (int c0 = 0; c0 < 64; c0 += 4) {
                float a4[4][4];
#pragma unroll
                for (int r = 0; r < 4; r++)
                    *reinterpret_cast<float4*>(a4[r]) =
                        *reinterpret_cast<const float4*>(F1 + (rg + r * 8) * S1 + c0);
#pragma unroll
                for (int cc = 0; cc < 4; cc++) {
                    const int c = c0 + cc;
                    const ulonglong2 wA = *reinterpret_cast<const ulonglong2*>(Wb + c * 128);
                    const ulonglong2 wB = *reinterpret_cast<const ulonglong2*>(Wb + c * 128 + 4);
#pragma unroll
                    for (int r = 0; r < 4; r++) {
                        const ull aa = pk2(a4[r][cc], a4[r][cc]);
                        acc[r][0] = fma2(aa, wA.x, acc[r][0]);
                        acc[r][1] = fma2(aa, wA.y, acc[r][1]);
                        acc[r][2] = fma2(aa, wB.x, acc[r][2]);
                        acc[r][3] = fma2(aa, wB.y, acc[r][3]);
                    }
                }
            }

            float* Ob = gp + (isQ ? GP_Q2 : GP_P2);
            ull bp[4];
            if (!isQ) {
                const ulonglong2 bA = *reinterpret_cast<const ulonglong2*>(sm + OFF_B2 + j0);
                const ulonglong2 bB = *reinterpret_cast<const ulonglong2*>(sm + OFF_B2 + j0 + 4);
                bp[0] = bA.x; bp[1] = bA.y; bp[2] = bB.x; bp[3] = bB.y;
            } else {
                bp[0] = bp[1] = bp[2] = bp[3] = 0ULL;
            }
#pragma unroll
            for (int r = 0; r < 4; r++) {
                const int row = rg + r * 8;
                ulonglong2 s0, s1;
                s0.x = add2(acc[r][0], bp[0]); s0.y = add2(acc[r][1], bp[1]);
                s1.x = add2(acc[r][2], bp[2]); s1.y = add2(acc[r][3], bp[3]);
                *reinterpret_cast<ulonglong2*>(Ob + row * S2 + j0)     = s0;
                *reinterpret_cast<ulonglong2*>(Ob + row * S2 + j0 + 4) = s1;
            }
        }
        group_bar(gid);

        // ---- edge phase 2 (chunked channels) + fused pooling ----
        {
            const int i = ltid >> 3, s = ltid & 7;
            float acc[16];
            edge_phase_fast<4, S2>(gp + GP_P2, gp + GP_Q2, gp + GP_XS, idxs,
                                   sm + OFF_G2, sm + OFF_BE2,
                                   1.f / 128.f, i, s, gid, npass2, acc);
#pragma unroll
            for (int c = 0; c < 16; c++) {
                acc[c] += __shfl_xor_sync(0xffffffffu, acc[c], 8);
                acc[c] += __shfl_xor_sync(0xffffffffu, acc[c], 16);
            }
            float* wb = gp + GP_FB;            // warpbuf[8][128]
            const int w = ltid >> 5;
            if ((ltid & 24) == 0) {
#pragma unroll
                for (int j = 0; j < 4; j++)
                    *reinterpret_cast<float4*>(wb + w * 128 + s * 4 + j * 32) =
                        *reinterpret_cast<float4*>(acc + j * 4);
            }
        }
        group_bar(gid);

        // ---- final pool: mean over 32 points -> g_pool[cloud][128] ----
        if (ltid < 128) {
            const float* wb = gp + GP_FB;
            float s = 0.f;
#pragma unroll
            for (int w = 0; w < 8; w++) s += wb[w * 128 + ltid];
            g_pool[cloud * C2 + ltid] = s * (1.f / 32.f);
        }
        group_bar(gid);   // pool reads done before next iteration reuses smem
    }
}

// out[4096,384] = g_pool[4096,128] @ Wo[128,384] + bo  (FFMA2, vectorized a)
__global__ __launch_bounds__(256)
void proj_kernel(const float* __restrict__ Wo, const float* __restrict__ bo,
                 float* __restrict__ out)
{
    extern __shared__ float sm2[];
    float* As = sm2;
    float* Ws = sm2 + 64 * 128;
    const int tid = threadIdx.x;
    const int row0 = blockIdx.x * 64;
    const int colB = blockIdx.y * 64;

    {
        const float4* ag = reinterpret_cast<const float4*>(g_pool + row0 * 128);
        float4* ad = reinterpret_cast<float4*>(As);
#pragma unroll
        for (int r = 0; r < 8; r++) ad[tid + r * 256] = ag[tid + r * 256];
    }
    for (int t = tid; t < 128 * 64; t += 256) {
        const int c = t >> 6, j = t & 63;
        Ws[t] = Wo[c * ECH + colB + j];
    }
    __syncthreads();

    const int r0 = (tid >> 4) * 4;
    const int c0 = (tid & 15) * 4;
    ull acc[4][2];
#pragma unroll
    for (int r = 0; r < 4; r++) { acc[r][0] = 0ULL; acc[r][1] = 0ULL; }

#pragma unroll 4
    for (int cb = 0; cb < 128; cb += 4) {
        float a4[4][4];
#pragma unroll
        for (int r = 0; r < 4; r++)
            *reinterpret_cast<float4*>(a4[r]) =
                *reinterpret_cast<const float4*>(As + (r0 + r) * 128 + cb);
#pragma unroll
        for (int cc = 0; cc < 4; cc++) {
            const ulonglong2 w = *reinterpret_cast<const ulonglong2*>(Ws + (cb + cc) * 64 + c0);
#pragma unroll
            for (int r = 0; r < 4; r++) {
                const ull aa = pk2(a4[r][cc], a4[r][cc]);
                acc[r][0] = fma2(aa, w.x, acc[r][0]);
                acc[r][1] = fma2(aa, w.y, acc[r][1]);
            }
        }
    }

    const ulonglong2 bb = *reinterpret_cast<const ulonglong2*>(bo + colB + c0);
#pragma unroll
    for (int r = 0; r < 4; r++) {
        ulonglong2 o;
        o.x = add2(acc[r][0], bb.x);
        o.y = add2(acc[r][1], bb.y);
        *reinterpret_cast<ulonglong2*>(out + (row0 + r0 + r) * ECH + colB + c0) = o;
    }
}

extern "C" void kernel_launch(void* const* d_in, const int* in_sizes, int n_in,
                              void* d_out, int out_size)
{
    const float* x   = (const float*)d_in[0];
    const float* W1  = (const float*)d_in[1];
    const float* b1  = (const float*)d_in[2];
    const float* g1  = (const float*)d_in[3];
    const float* be1 = (const float*)d_in[4];
    const float* W2  = (const float*)d_in[5];
    const float* b2  = (const float*)d_in[6];
    const float* g2  = (const float*)d_in[7];
    const float* be2 = (const float*)d_in[8];
    const float* Wo  = (const float*)d_in[9];
    const float* bo  = (const float*)d_in[10];
    float* out = (float*)d_out;

    cudaFuncSetAttribute(knn_encoder_kernel,
                         cudaFuncAttributeMaxDynamicSharedMemorySize, SMEM1_BYTES);
    cudaFuncSetAttribute(proj_kernel,
                         cudaFuncAttributeMaxDynamicSharedMemorySize, SMEM2_BYTES);

    void* tk_addr = nullptr;
    cudaGetSymbolAddress(&tk_addr, g_ticket);
    cudaMemsetAsync(tk_addr, 0, sizeof(unsigned));

    knn_encoder_kernel<<<NBLK, NTH, SMEM1_BYTES>>>(
        x, W1, b1, g1, be1, W2, b2, g2, be2);
    proj_kernel<<<dim3(NC / 64, ECH / 64), 256, SMEM2_BYTES>>>(Wo, bo, out);
}

// round 13
// speedup vs baseline: 1.1546x; 1.1546x over previous
#include <cuda_runtime.h>
#include <math.h>
#include <float.h>

#define NC   4096
#define NP   32
#define KNB  8
#define C1   64
#define C2   128
#define S1   68
#define S2   132
#define ECH  384
#define NGRP 3
#define NTH  (NGRP * 256)

typedef unsigned long long ull;

// ---- shared (block-common) smem layout, float words ----
#define OFF_W2    0                          // 16384
#define OFF_W1    (OFF_W2 + 16384)           // 384
#define OFF_B1    (OFF_W1 + 384)
#define OFF_G1    (OFF_B1 + 64)
#define OFF_BE1   (OFF_G1 + 64)
#define OFF_B2    (OFF_BE1 + 64)
#define OFF_G2    (OFF_B2 + 128)
#define OFF_BE2   (OFF_G2 + 128)
#define OFF_FLAGS (OFF_BE2 + 128)            // 6 int flags (any g<=0 per loader warp)
#define SHARED_WORDS (OFF_FLAGS + 8)

// ---- per-group smem layout ----
#define GP_P1   0
#define GP_Q1   2176
#define GP_P2   0
#define GP_Q2   4224
#define GP_FB   8448                        // F1 during GEMM; warpbuf during edge2
#define GP_XS   (GP_FB + 2176)              // 96: x; also sumV table inside edge phases
#define GP_IDX  (GP_XS + 96)                // 256 ints
#define GRP_WORDS (GP_IDX + 256)

#define SMEM1_WORDS (SHARED_WORDS + NGRP * GRP_WORDS)
#define SMEM1_BYTES (SMEM1_WORDS * 4)

#define SMEM2_BYTES ((64*128 + 128*64) * 4)

__device__ float g_pool[NC * C2];

// ---- packed f32x2 helpers ----
__device__ __forceinline__ ull pk2(float lo, float hi) {
    ull r; asm("mov.b64 %0, {%1, %2};" : "=l"(r) : "f"(lo), "f"(hi)); return r;
}
__device__ __forceinline__ void upk2(ull v, float& lo, float& hi) {
    asm("mov.b64 {%0, %1}, %2;" : "=f"(lo), "=f"(hi) : "l"(v));
}
__device__ __forceinline__ ull fma2(ull a, ull b, ull c) {
    ull d; asm("fma.rn.f32x2 %0, %1, %2, %3;" : "=l"(d) : "l"(a), "l"(b), "l"(c)); return d;
}
__device__ __forceinline__ ull add2(ull a, ull b) {
    ull d; asm("add.rn.f32x2 %0, %1, %2;" : "=l"(d) : "l"(a), "l"(b)); return d;
}

__device__ __forceinline__ float elu_f(float x) {
    return x > 0.f ? x : (__expf(x) - 1.f);
}

__device__ __forceinline__ void group_bar(int gid) {
    asm volatile("bar.sync %0, %1;" :: "r"(gid + 1), "r"(256) : "memory");
}

// Tiny no-op kernel: occupies launch slots 1-5 so ncu's "-s 5 -c 1" capture
// lands on knn_encoder_kernel (launch 6) instead of proj_kernel.
__global__ void dummy_kernel() {}

// Edge phase, mu-trick + zmax-only + uniform npass cold path.
// Thread (i,s) owns NCHUNK float4 chunks: channels {s*4 + j*32 + l}.
// Chunk offsets s*4 mod 32 are distinct across the octet -> conflict-free LDS.
// Neighbor indices hoisted into registers (2x int4) before the pass loop.
template<int NCHUNK, int STRIDE>
__device__ __forceinline__ void edge_phase_fast(
    const float* __restrict__ U, const float* __restrict__ V,
    float* __restrict__ sumVsm, const int* __restrict__ idxs,
    const float* __restrict__ gvec, const float* __restrict__ bevec,
    float invC, int i, int s, int gid, int npass, float* __restrict__ o)
{
    constexpr int P = 2 * NCHUNK;            // ull pairs
    const int base = s * 4;
    ull u[P];
    {
#pragma unroll
        for (int j = 0; j < NCHUNK; j++) {
            const ulonglong2 t = *reinterpret_cast<const ulonglong2*>(U + i * STRIDE + base + j * 32);
            u[2*j] = t.x; u[2*j+1] = t.y;
        }
    }
    float sumU, sumV;
    {
        ull su = 0ULL;
#pragma unroll
        for (int p = 0; p < P; p++) su = add2(su, u[p]);
        float a, b; upk2(su, a, b); sumU = a + b;

        ull sv = 0ULL;
#pragma unroll
        for (int j = 0; j < NCHUNK; j++) {
            const ulonglong2 t = *reinterpret_cast<const ulonglong2*>(V + i * STRIDE + base + j * 32);
            sv = add2(sv, t.x); sv = add2(sv, t.y);
        }
        upk2(sv, a, b); sumV = a + b;
    }
#pragma unroll
    for (int off = 1; off < 8; off <<= 1) {
        sumU += __shfl_xor_sync(0xffffffffu, sumU, off);
        sumV += __shfl_xor_sync(0xffffffffu, sumV, off);
    }
    if (s == 0) sumVsm[i] = sumV;
    group_bar(gid);

    // hoist the 8 neighbor indices (broadcast LDS.128 x2, constant-indexed after unroll)
    int nb[8];
    {
        const int4 n0 = *reinterpret_cast<const int4*>(idxs + i * KNB);
        const int4 n1 = *reinterpret_cast<const int4*>(idxs + i * KNB + 4);
        nb[0] = n0.x; nb[1] = n0.y; nb[2] = n0.z; nb[3] = n0.w;
        nb[4] = n1.x; nb[5] = n1.y; nb[6] = n1.z; nb[7] = n1.w;
    }

    float sgn = 1.f;
#pragma unroll 1
    for (int pass = 0; pass < npass; pass++, sgn = -1.f) {
        float zx[4 * NCHUNK];
#pragma unroll
        for (int c = 0; c < 4 * NCHUNK; c++) zx[c] = -FLT_MAX;

#pragma unroll
        for (int k = 0; k < KNB; k++) {
            const int n = nb[k];
            const float mu = (sumU + sumVsm[n]) * invC;
            ull t[P];
            ull ss2 = 0ULL;
#pragma unroll
            for (int j = 0; j < NCHUNK; j++) {
                const ulonglong2 vv = *reinterpret_cast<const ulonglong2*>(V + n * STRIDE + base + j * 32);
                const ull t0 = add2(u[2*j],   vv.x);
                const ull t1 = add2(u[2*j+1], vv.y);
                t[2*j] = t0; t[2*j+1] = t1;
                ss2 = fma2(t0, t0, ss2); ss2 = fma2(t1, t1, ss2);
            }
            float ql, qh; upk2(ss2, ql, qh);
            float ss = ql + qh;
#pragma unroll
            for (int off = 1; off < 8; off <<= 1)
                ss += __shfl_xor_sync(0xffffffffu, ss, off);
            const float var = fmaxf(fmaf(-mu, mu, ss * invC), 0.f);
            const float rstd = rsqrtf(var + 1e-5f) * sgn;
            const ull rr = pk2(rstd, rstd);
            const float nm = -mu * rstd;
            const ull nn = pk2(nm, nm);
#pragma unroll
            for (int p = 0; p < P; p++) {
                const ull z2 = fma2(t[p], rr, nn);
                float zl, zh; upk2(z2, zl, zh);
                zx[2*p]   = fmaxf(zx[2*p],   zl);
                zx[2*p+1] = fmaxf(zx[2*p+1], zh);
            }
        }
#pragma unroll
        for (int j = 0; j < NCHUNK; j++) {
#pragma unroll
            for (int l = 0; l < 4; l++) {
                const int c = 4*j + l;
                const int ch = base + j * 32 + l;
                const float gv = gvec[ch];
                const bool take = (pass == 0) ? (gv > 0.f) : (gv <= 0.f);
                if (take) {
                    const float zz = (pass == 0) ? zx[c] : -zx[c];
                    o[c] = elu_f(fmaf(gv, zz, bevec[ch]));
                }
            }
        }
    }
}

__global__ __launch_bounds__(NTH, 1)
void knn_encoder_kernel(
    const float* __restrict__ x,
    const float* __restrict__ W1, const float* __restrict__ b1,
    const float* __restrict__ g1, const float* __restrict__ be1,
    const float* __restrict__ W2, const float* __restrict__ b2,
    const float* __restrict__ g2, const float* __restrict__ be2)
{
    extern __shared__ float sm[];
    const int tid = threadIdx.x;
    const int gid = tid >> 8;
    const int ltid = tid & 255;
    const int cloud = blockIdx.x * NGRP + gid;
    const bool live = (cloud < NC);

    float* gp = sm + SHARED_WORDS + gid * GRP_WORDS;
    int* idxs = reinterpret_cast<int*>(gp + GP_IDX);
    int* flags = reinterpret_cast<int*>(sm + OFF_FLAGS);

    // ---- block-common params (loader warps also compute any(g<=0) flags) ----
    if (tid < 384) sm[OFF_W1 + tid] = W1[tid];
    if (tid >= 384 && tid < 448) {
        int j = tid - 384;
        float gv = g1[j];
        sm[OFF_B1 + j] = b1[j]; sm[OFF_G1 + j] = gv; sm[OFF_BE1 + j] = be1[j];
        int any = __any_sync(0xffffffffu, gv <= 0.f);
        if ((tid & 31) == 0) flags[(tid - 384) >> 5] = any;
    }
    if (tid >= 448 && tid < 576) {
        int j = tid - 448;
        float gv = g2[j];
        sm[OFF_B2 + j] = b2[j]; sm[OFF_G2 + j] = gv; sm[OFF_BE2 + j] = be2[j];
        int any = __any_sync(0xffffffffu, gv <= 0.f);
        if ((tid & 31) == 0) flags[2 + ((tid - 448) >> 5)] = any;
    }
    {
        const float4* src = reinterpret_cast<const float4*>(W2);
        float4* dst = reinterpret_cast<float4*>(sm + OFF_W2);
        for (int t = tid; t < 4096; t += NTH) dst[t] = src[t];
    }
    if (live && ltid < 96) gp[GP_XS + ltid] = x[cloud * NP * 3 + ltid];
    __syncthreads();

    const int npass1 = 1 + ((flags[0] | flags[1]) ? 1 : 0);
    const int npass2 = 1 + ((flags[2] | flags[3] | flags[4] | flags[5]) ? 1 : 0);

    if (live) {
        // ---- KNN (warp 0: per-point insertion sort) || conv1 (warps 1-7) ----
        if (ltid < 32) {
            const int i = ltid;
            const float xi0 = gp[GP_XS + i * 3 + 0];
            const float xi1 = gp[GP_XS + i * 3 + 1];
            const float xi2 = gp[GP_XS + i * 3 + 2];
            const float si = xi0 * xi0 + xi1 * xi1 + xi2 * xi2;
            float d[8]; int id[8];
#pragma unroll
            for (int j = 0; j < 8; j++) { d[j] = FLT_MAX; id[j] = 32; }
#pragma unroll 4
            for (int m = 0; m < 32; m++) {
                const float xm0 = gp[GP_XS + m * 3 + 0];
                const float xm1 = gp[GP_XS + m * 3 + 1];
                const float xm2 = gp[GP_XS + m * 3 + 2];
                const float smq = xm0 * xm0 + xm1 * xm1 + xm2 * xm2;
                const float dot = xi0 * xm0 + xi1 * xm1 + xi2 * xm2;
                float nd = si + smq - 2.f * dot;
                int ni = m;
#pragma unroll
                for (int j = 0; j < 8; j++) {
                    const bool lt = nd < d[j];
                    const float td = d[j]; const int ti = id[j];
                    d[j]  = lt ? nd : td;  id[j] = lt ? ni : ti;
                    nd    = lt ? td : nd;  ni    = lt ? ti : ni;
                }
            }
#pragma unroll
            for (int j = 0; j < 8; j++) idxs[i * KNB + j] = id[j];
        } else {
            for (int o = ltid - 32; o < NP * C1; o += 224) {
                const int i = o >> 6, j = o & 63;
                const float x0 = gp[GP_XS + i * 3 + 0];
                const float x1 = gp[GP_XS + i * 3 + 1];
                const float x2 = gp[GP_XS + i * 3 + 2];
                float p = sm[OFF_B1 + j];
                p = fmaf(x0, sm[OFF_W1 + j], p);
                p = fmaf(x1, sm[OFF_W1 + 64 + j], p);
                p = fmaf(x2, sm[OFF_W1 + 128 + j], p);
                float q = x0 * sm[OFF_W1 + 192 + j];
                q = fmaf(x1, sm[OFF_W1 + 256 + j], q);
                q = fmaf(x2, sm[OFF_W1 + 320 + j], q);
                gp[GP_P1 + i * S1 + j] = p;
                gp[GP_Q1 + i * S1 + j] = q;
            }
        }
        group_bar(gid);

        // ---- edge phase 1 -> F1[32][64] (chunked channels, conflict-free) ----
        {
            const int i = ltid >> 3, s = ltid & 7;
            float o[8];
            edge_phase_fast<2, S1>(gp + GP_P1, gp + GP_Q1, gp + GP_XS, idxs,
                                   sm + OFF_G1, sm + OFF_BE1,
                                   1.f / 64.f, i, s, gid, npass1, o);
            float* F1 = gp + GP_FB;
            *reinterpret_cast<float4*>(F1 + i * S1 + s * 4)      = *reinterpret_cast<float4*>(o);
            *reinterpret_cast<float4*>(F1 + i * S1 + s * 4 + 32) = *reinterpret_cast<float4*>(o + 4);
        }
        group_bar(gid);

        // ---- conv2 P/Q GEMM (FFMA2, vectorized a-loads) ----
        {
            const int rg = ltid & 7;
            const int cg = ltid >> 3;
            const int j0 = (cg & 15) * 8;
            const bool isQ = (cg & 16) != 0;
            const float* Wb = sm + OFF_W2 + (isQ ? 64 * 128 : 0) + j0;
            const float* F1 = gp + GP_FB;
            ull acc[4][4];
#pragma unroll
            for (int r = 0; r < 4; r++)
#pragma unroll
                for (int p = 0; p < 4; p++) acc[r][p] = 0ULL;

#pragma unroll 4
            for (int c0 = 0; c0 < 64; c0 += 4) {
                float a4[4][4];
#pragma unroll
                for (int r = 0; r < 4; r++)
                    *reinterpret_cast<float4*>(a4[r]) =
                        *reinterpret_cast<const float4*>(F1 + (rg + r * 8) * S1 + c0);
#pragma unroll
                for (int cc = 0; cc < 4; cc++) {
                    const int c = c0 + cc;
                    const ulonglong2 wA = *reinterpret_cast<const ulonglong2*>(Wb + c * 128);
                    const ulonglong2 wB = *reinterpret_cast<const ulonglong2*>(Wb + c * 128 + 4);
#pragma unroll
                    for (int r = 0; r < 4; r++) {
                        const ull aa = pk2(a4[r][cc], a4[r][cc]);
                        acc[r][0] = fma2(aa, wA.x, acc[r][0]);
                        acc[r][1] = fma2(aa, wA.y, acc[r][1]);
                        acc[r][2] = fma2(aa, wB.x, acc[r][2]);
                        acc[r][3] = fma2(aa, wB.y, acc[r][3]);
                    }
                }
            }

            float* Ob = gp + (isQ ? GP_Q2 : GP_P2);
            ull bp[4];
            if (!isQ) {
                const ulonglong2 bA = *reinterpret_cast<const ulonglong2*>(sm + OFF_B2 + j0);
                const ulonglong2 bB = *reinterpret_cast<const ulonglong2*>(sm + OFF_B2 + j0 + 4);
                bp[0] = bA.x; bp[1] = bA.y; bp[2] = bB.x; bp[3] = bB.y;
            } else {
                bp[0] = bp[1] = bp[2] = bp[3] = 0ULL;
            }
#pragma unroll
            for (int r = 0; r < 4; r++) {
                const int row = rg + r * 8;
                ulonglong2 s0, s1;
                s0.x = add2(acc[r][0], bp[0]); s0.y = add2(acc[r][1], bp[1]);
                s1.x = add2(acc[r][2], bp[2]); s1.y = add2(acc[r][3], bp[3]);
                *reinterpret_cast<ulonglong2*>(Ob + row * S2 + j0)     = s0;
                *reinterpret_cast<ulonglong2*>(Ob + row * S2 + j0 + 4) = s1;
            }
        }
        group_bar(gid);

        // ---- edge phase 2 (chunked channels) + fused pooling ----
        {
            const int i = ltid >> 3, s = ltid & 7;
            float acc[16];
            edge_phase_fast<4, S2>(gp + GP_P2, gp + GP_Q2, gp + GP_XS, idxs,
                                   sm + OFF_G2, sm + OFF_BE2,
                                   1.f / 128.f, i, s, gid, npass2, acc);
#pragma unroll
            for (int c = 0; c < 16; c++) {
                acc[c] += __shfl_xor_sync(0xffffffffu, acc[c], 8);
                acc[c] += __shfl_xor_sync(0xffffffffu, acc[c], 16);
            }
            float* wb = gp + GP_FB;            // warpbuf[8][128]
            const int w = ltid >> 5;
            if ((ltid & 24) == 0) {
#pragma unroll
                for (int j = 0; j < 4; j++)
                    *reinterpret_cast<float4*>(wb + w * 128 + s * 4 + j * 32) =
                        *reinterpret_cast<float4*>(acc + j * 4);
            }
        }
        group_bar(gid);

        // ---- final pool: mean over 32 points -> g_pool[cloud][128] ----
        if (ltid < 128) {
            const float* wb = gp + GP_FB;
            float s = 0.f;
#pragma unroll
            for (int w = 0; w < 8; w++) s += wb[w * 128 + ltid];
            g_pool[cloud * C2 + ltid] = s * (1.f / 32.f);
        }
    }
}

// out[4096,384] = g_pool[4096,128] @ Wo[128,384] + bo  (FFMA2, vectorized a)
__global__ __launch_bounds__(256)
void proj_kernel(const float* __restrict__ Wo, const float* __restrict__ bo,
                 float* __restrict__ out)
{
    extern __shared__ float sm2[];
    float* As = sm2;
    float* Ws = sm2 + 64 * 128;
    const int tid = threadIdx.x;
    const int row0 = blockIdx.x * 64;
    const int colB = blockIdx.y * 64;

    {
        const float4* ag = reinterpret_cast<const float4*>(g_pool + row0 * 128);
        float4* ad = reinterpret_cast<float4*>(As);
#pragma unroll
        for (int r = 0; r < 8; r++) ad[tid + r * 256] = ag[tid + r * 256];
    }
    for (int t = tid; t < 128 * 64; t += 256) {
        const int c = t >> 6, j = t & 63;
        Ws[t] = Wo[c * ECH + colB + j];
    }
    __syncthreads();

    const int r0 = (tid >> 4) * 4;
    const int c0 = (tid & 15) * 4;
    ull acc[4][2];
#pragma unroll
    for (int r = 0; r < 4; r++) { acc[r][0] = 0ULL; acc[r][1] = 0ULL; }

#pragma unroll 4
    for (int cb = 0; cb < 128; cb += 4) {
        float a4[4][4];
#pragma unroll
        for (int r = 0; r < 4; r++)
            *reinterpret_cast<float4*>(a4[r]) =
                *reinterpret_cast<const float4*>(As + (r0 + r) * 128 + cb);
#pragma unroll
        for (int cc = 0; cc < 4; cc++) {
            const ulonglong2 w = *reinterpret_cast<const ulonglong2*>(Ws + (cb + cc) * 64 + c0);
#pragma unroll
            for (int r = 0; r < 4; r++) {
                const ull aa = pk2(a4[r][cc], a4[r][cc]);
                acc[r][0] = fma2(aa, w.x, acc[r][0]);
                acc[r][1] = fma2(aa, w.y, acc[r][1]);
            }
        }
    }

    const ulonglong2 bb = *reinterpret_cast<const ulonglong2*>(bo + colB + c0);
#pragma unroll
    for (int r = 0; r < 4; r++) {
        ulonglong2 o;
        o.x = add2(acc[r][0], bb.x);
        o.y = add2(acc[r][1], bb.y);
        *reinterpret_cast<ulonglong2*>(out + (row0 + r0 + r) * ECH + colB + c0) = o;
    }
}

extern "C" void kernel_launch(void* const* d_in, const int* in_sizes, int n_in,
                              void* d_out, int out_size)
{
    const float* x   = (const float*)d_in[0];
    const float* W1  = (const float*)d_in[1];
    const float* b1  = (const float*)d_in[2];
    const float* g1  = (const float*)d_in[3];
    const float* be1 = (const float*)d_in[4];
    const float* W2  = (const float*)d_in[5];
    const float* b2  = (const float*)d_in[6];
    const float* g2  = (const float*)d_in[7];
    const float* be2 = (const float*)d_in[8];
    const float* Wo  = (const float*)d_in[9];
    const float* bo  = (const float*)d_in[10];
    float* out = (float*)d_out;

    cudaFuncSetAttribute(knn_encoder_kernel,
                         cudaFuncAttributeMaxDynamicSharedMemorySize, SMEM1_BYTES);
    cudaFuncSetAttribute(proj_kernel,
                         cudaFuncAttributeMaxDynamicSharedMemorySize, SMEM2_BYTES);

    // 5 no-op launches so ncu's "-s 5 -c 1" captures knn_encoder_kernel
    // (launch #6) instead of proj_kernel. Graph-capturable, deterministic.
    for (int i = 0; i < 5; i++) dummy_kernel<<<1, 32>>>();

    knn_encoder_kernel<<<(NC + NGRP - 1) / NGRP, NTH, SMEM1_BYTES>>>(
        x, W1, b1, g1, be1, W2, b2, g2, be2);
    proj_kernel<<<dim3(NC / 64, ECH / 64), 256, SMEM2_BYTES>>>(Wo, bo, out);
}

// round 14
// speedup vs baseline: 1.1981x; 1.0377x over previous
#include <cuda_runtime.h>
#include <math.h>
#include <float.h>

#define NC   4096
#define NP   32
#define KNB  8
#define C1   64
#define C2   128
#define S1   68
#define S2   132
#define ECH  384
#define NGRP 3
#define NTH  (NGRP * 256)

typedef unsigned long long ull;

// ---- shared (block-common) smem layout, float words ----
#define OFF_W2    0                          // 16384
#define OFF_W1    (OFF_W2 + 16384)           // 384
#define OFF_B1    (OFF_W1 + 384)
#define OFF_G1    (OFF_B1 + 64)
#define OFF_BE1   (OFF_G1 + 64)
#define OFF_B2    (OFF_BE1 + 64)
#define OFF_G2    (OFF_B2 + 128)
#define OFF_BE2   (OFF_G2 + 128)
#define OFF_FLAGS (OFF_BE2 + 128)            // 6 int flags (any g<=0 per loader warp)
#define SHARED_WORDS (OFF_FLAGS + 8)

// ---- per-group smem layout ----
#define GP_P1   0
#define GP_Q1   2176
#define GP_P2   0
#define GP_Q2   4224
#define GP_FB   8448                        // F1 during GEMM; warpbuf during edge2
#define GP_XS   (GP_FB + 2176)              // 96: x; also sumV table inside edge phases
#define GP_IDX  (GP_XS + 96)                // 256 ints
#define GRP_WORDS (GP_IDX + 256)

#define SMEM1_WORDS (SHARED_WORDS + NGRP * GRP_WORDS)
#define SMEM1_BYTES (SMEM1_WORDS * 4)

#define SMEM2_BYTES ((64*128 + 128*64) * 4)

__device__ float g_pool[NC * C2];

// ---- packed f32x2 helpers ----
__device__ __forceinline__ ull pk2(float lo, float hi) {
    ull r; asm("mov.b64 %0, {%1, %2};" : "=l"(r) : "f"(lo), "f"(hi)); return r;
}
__device__ __forceinline__ void upk2(ull v, float& lo, float& hi) {
    asm("mov.b64 {%0, %1}, %2;" : "=f"(lo), "=f"(hi) : "l"(v));
}
__device__ __forceinline__ ull fma2(ull a, ull b, ull c) {
    ull d; asm("fma.rn.f32x2 %0, %1, %2, %3;" : "=l"(d) : "l"(a), "l"(b), "l"(c)); return d;
}
__device__ __forceinline__ ull add2(ull a, ull b) {
    ull d; asm("add.rn.f32x2 %0, %1, %2;" : "=l"(d) : "l"(a), "l"(b)); return d;
}

__device__ __forceinline__ float elu_f(float x) {
    return x > 0.f ? x : (__expf(x) - 1.f);
}

__device__ __forceinline__ void group_bar(int gid) {
    asm volatile("bar.sync %0, %1;" :: "r"(gid + 1), "r"(256) : "memory");
}

// Edge phase, mu-trick + zmax-only + uniform npass cold path.
// Thread (i,s) owns NCHUNK float4 chunks: channels {s*4 + j*32 + l}.
// Chunk offsets s*4 mod 32 are distinct across the octet -> conflict-free LDS.
// Neighbor indices hoisted into registers (2x int4) before the pass loop.
template<int NCHUNK, int STRIDE>
__device__ __forceinline__ void edge_phase_fast(
    const float* __restrict__ U, const float* __restrict__ V,
    float* __restrict__ sumVsm, const int* __restrict__ idxs,
    const float* __restrict__ gvec, const float* __restrict__ bevec,
    float invC, int i, int s, int gid, int npass, float* __restrict__ o)
{
    constexpr int P = 2 * NCHUNK;            // ull pairs
    const int base = s * 4;
    ull u[P];
    {
#pragma unroll
        for (int j = 0; j < NCHUNK; j++) {
            const ulonglong2 t = *reinterpret_cast<const ulonglong2*>(U + i * STRIDE + base + j * 32);
            u[2*j] = t.x; u[2*j+1] = t.y;
        }
    }
    float sumU, sumV;
    {
        ull su = 0ULL;
#pragma unroll
        for (int p = 0; p < P; p++) su = add2(su, u[p]);
        float a, b; upk2(su, a, b); sumU = a + b;

        ull sv = 0ULL;
#pragma unroll
        for (int j = 0; j < NCHUNK; j++) {
            const ulonglong2 t = *reinterpret_cast<const ulonglong2*>(V + i * STRIDE + base + j * 32);
            sv = add2(sv, t.x); sv = add2(sv, t.y);
        }
        upk2(sv, a, b); sumV = a + b;
    }
#pragma unroll
    for (int off = 1; off < 8; off <<= 1) {
        sumU += __shfl_xor_sync(0xffffffffu, sumU, off);
        sumV += __shfl_xor_sync(0xffffffffu, sumV, off);
    }
    if (s == 0) sumVsm[i] = sumV;
    group_bar(gid);

    // hoist the 8 neighbor indices (2x broadcast LDS.128, constant-indexed after unroll)
    int nb[8];
    {
        const int4 n0 = *reinterpret_cast<const int4*>(idxs + i * KNB);
        const int4 n1 = *reinterpret_cast<const int4*>(idxs + i * KNB + 4);
        nb[0] = n0.x; nb[1] = n0.y; nb[2] = n0.z; nb[3] = n0.w;
        nb[4] = n1.x; nb[5] = n1.y; nb[6] = n1.z; nb[7] = n1.w;
    }

    float sgn = 1.f;
#pragma unroll 1
    for (int pass = 0; pass < npass; pass++, sgn = -1.f) {
        float zx[4 * NCHUNK];
#pragma unroll
        for (int c = 0; c < 4 * NCHUNK; c++) zx[c] = -FLT_MAX;

#pragma unroll
        for (int k = 0; k < KNB; k++) {
            const int n = nb[k];
            const float mu = (sumU + sumVsm[n]) * invC;
            ull t[P];
            ull ss2 = 0ULL;
#pragma unroll
            for (int j = 0; j < NCHUNK; j++) {
                const ulonglong2 vv = *reinterpret_cast<const ulonglong2*>(V + n * STRIDE + base + j * 32);
                const ull t0 = add2(u[2*j],   vv.x);
                const ull t1 = add2(u[2*j+1], vv.y);
                t[2*j] = t0; t[2*j+1] = t1;
                ss2 = fma2(t0, t0, ss2); ss2 = fma2(t1, t1, ss2);
            }
            float ql, qh; upk2(ss2, ql, qh);
            float ss = ql + qh;
#pragma unroll
            for (int off = 1; off < 8; off <<= 1)
                ss += __shfl_xor_sync(0xffffffffu, ss, off);
            const float var = fmaxf(fmaf(-mu, mu, ss * invC), 0.f);
            const float rstd = rsqrtf(var + 1e-5f) * sgn;
            const ull rr = pk2(rstd, rstd);
            const float nm = -mu * rstd;
            const ull nn = pk2(nm, nm);
#pragma unroll
            for (int p = 0; p < P; p++) {
                const ull z2 = fma2(t[p], rr, nn);
                float zl, zh; upk2(z2, zl, zh);
                zx[2*p]   = fmaxf(zx[2*p],   zl);
                zx[2*p+1] = fmaxf(zx[2*p+1], zh);
            }
        }
#pragma unroll
        for (int j = 0; j < NCHUNK; j++) {
#pragma unroll
            for (int l = 0; l < 4; l++) {
                const int c = 4*j + l;
                const int ch = base + j * 32 + l;
                const float gv = gvec[ch];
                const bool take = (pass == 0) ? (gv > 0.f) : (gv <= 0.f);
                if (take) {
                    const float zz = (pass == 0) ? zx[c] : -zx[c];
                    o[c] = elu_f(fmaf(gv, zz, bevec[ch]));
                }
            }
        }
    }
}

__global__ __launch_bounds__(NTH, 1)
void knn_encoder_kernel(
    const float* __restrict__ x,
    const float* __restrict__ W1, const float* __restrict__ b1,
    const float* __restrict__ g1, const float* __restrict__ be1,
    const float* __restrict__ W2, const float* __restrict__ b2,
    const float* __restrict__ g2, const float* __restrict__ be2)
{
    extern __shared__ float sm[];
    const int tid = threadIdx.x;
    const int gid = tid >> 8;
    const int ltid = tid & 255;
    const int cloud = blockIdx.x * NGRP + gid;
    const bool live = (cloud < NC);

    float* gp = sm + SHARED_WORDS + gid * GRP_WORDS;
    int* idxs = reinterpret_cast<int*>(gp + GP_IDX);
    int* flags = reinterpret_cast<int*>(sm + OFF_FLAGS);

    // ---- block-common params (loader warps also compute any(g<=0) flags) ----
    if (tid < 384) sm[OFF_W1 + tid] = W1[tid];
    if (tid >= 384 && tid < 448) {
        int j = tid - 384;
        float gv = g1[j];
        sm[OFF_B1 + j] = b1[j]; sm[OFF_G1 + j] = gv; sm[OFF_BE1 + j] = be1[j];
        int any = __any_sync(0xffffffffu, gv <= 0.f);
        if ((tid & 31) == 0) flags[(tid - 384) >> 5] = any;
    }
    if (tid >= 448 && tid < 576) {
        int j = tid - 448;
        float gv = g2[j];
        sm[OFF_B2 + j] = b2[j]; sm[OFF_G2 + j] = gv; sm[OFF_BE2 + j] = be2[j];
        int any = __any_sync(0xffffffffu, gv <= 0.f);
        if ((tid & 31) == 0) flags[2 + ((tid - 448) >> 5)] = any;
    }
    {
        const float4* src = reinterpret_cast<const float4*>(W2);
        float4* dst = reinterpret_cast<float4*>(sm + OFF_W2);
        for (int t = tid; t < 4096; t += NTH) dst[t] = src[t];
    }
    if (live && ltid < 96) gp[GP_XS + ltid] = x[cloud * NP * 3 + ltid];
    __syncthreads();

    const int npass1 = 1 + ((flags[0] | flags[1]) ? 1 : 0);
    const int npass2 = 1 + ((flags[2] | flags[3] | flags[4] | flags[5]) ? 1 : 0);

    if (live) {
        // ---- KNN (warp 0: per-point insertion sort) || conv1 (warps 1-7) ----
        if (ltid < 32) {
            const int i = ltid;
            const float xi0 = gp[GP_XS + i * 3 + 0];
            const float xi1 = gp[GP_XS + i * 3 + 1];
            const float xi2 = gp[GP_XS + i * 3 + 2];
            const float si = xi0 * xi0 + xi1 * xi1 + xi2 * xi2;
            float d[8]; int id[8];
#pragma unroll
            for (int j = 0; j < 8; j++) { d[j] = FLT_MAX; id[j] = 32; }
#pragma unroll 4
            for (int m = 0; m < 32; m++) {
                const float xm0 = gp[GP_XS + m * 3 + 0];
                const float xm1 = gp[GP_XS + m * 3 + 1];
                const float xm2 = gp[GP_XS + m * 3 + 2];
                const float smq = xm0 * xm0 + xm1 * xm1 + xm2 * xm2;
                const float dot = xi0 * xm0 + xi1 * xm1 + xi2 * xm2;
                float nd = si + smq - 2.f * dot;
                int ni = m;
#pragma unroll
                for (int j = 0; j < 8; j++) {
                    const bool lt = nd < d[j];
                    const float td = d[j]; const int ti = id[j];
                    d[j]  = lt ? nd : td;  id[j] = lt ? ni : ti;
                    nd    = lt ? td : nd;  ni    = lt ? ti : ni;
                }
            }
#pragma unroll
            for (int j = 0; j < 8; j++) idxs[i * KNB + j] = id[j];
        } else {
            for (int o = ltid - 32; o < NP * C1; o += 224) {
                const int i = o >> 6, j = o & 63;
                const float x0 = gp[GP_XS + i * 3 + 0];
                const float x1 = gp[GP_XS + i * 3 + 1];
                const float x2 = gp[GP_XS + i * 3 + 2];
                float p = sm[OFF_B1 + j];
                p = fmaf(x0, sm[OFF_W1 + j], p);
                p = fmaf(x1, sm[OFF_W1 + 64 + j], p);
                p = fmaf(x2, sm[OFF_W1 + 128 + j], p);
                float q = x0 * sm[OFF_W1 + 192 + j];
                q = fmaf(x1, sm[OFF_W1 + 256 + j], q);
                q = fmaf(x2, sm[OFF_W1 + 320 + j], q);
                gp[GP_P1 + i * S1 + j] = p;
                gp[GP_Q1 + i * S1 + j] = q;
            }
        }
        group_bar(gid);

        // ---- edge phase 1 -> F1[32][64] (chunked channels, conflict-free) ----
        {
            const int i = ltid >> 3, s = ltid & 7;
            float o[8];
            edge_phase_fast<2, S1>(gp + GP_P1, gp + GP_Q1, gp + GP_XS, idxs,
                                   sm + OFF_G1, sm + OFF_BE1,
                                   1.f / 64.f, i, s, gid, npass1, o);
            float* F1 = gp + GP_FB;
            *reinterpret_cast<float4*>(F1 + i * S1 + s * 4)      = *reinterpret_cast<float4*>(o);
            *reinterpret_cast<float4*>(F1 + i * S1 + s * 4 + 32) = *reinterpret_cast<float4*>(o + 4);
        }
        group_bar(gid);

        // ---- conv2 P/Q GEMM (FFMA2, vectorized a-loads, deep unroll) ----
        {
            const int rg = ltid & 7;
            const int cg = ltid >> 3;
            const int j0 = (cg & 15) * 8;
            const bool isQ = (cg & 16) != 0;
            const float* Wb = sm + OFF_W2 + (isQ ? 64 * 128 : 0) + j0;
            const float* F1 = gp + GP_FB;
            ull acc[4][4];
#pragma unroll
            for (int r = 0; r < 4; r++)
#pragma unroll
                for (int p = 0; p < 4; p++) acc[r][p] = 0ULL;

#pragma unroll 8
            for (int c0 = 0; c0 < 64; c0 += 4) {
                float a4[4][4];
#pragma unroll
                for (int r = 0; r < 4; r++)
                    *reinterpret_cast<float4*>(a4[r]) =
                        *reinterpret_cast<const float4*>(F1 + (rg + r * 8) * S1 + c0);
#pragma unroll
                for (int cc = 0; cc < 4; cc++) {
                    const int c = c0 + cc;
                    const ulonglong2 wA = *reinterpret_cast<const ulonglong2*>(Wb + c * 128);
                    const ulonglong2 wB = *reinterpret_cast<const ulonglong2*>(Wb + c * 128 + 4);
#pragma unroll
                    for (int r = 0; r < 4; r++) {
                        const ull aa = pk2(a4[r][cc], a4[r][cc]);
                        acc[r][0] = fma2(aa, wA.x, acc[r][0]);
                        acc[r][1] = fma2(aa, wA.y, acc[r][1]);
                        acc[r][2] = fma2(aa, wB.x, acc[r][2]);
                        acc[r][3] = fma2(aa, wB.y, acc[r][3]);
                    }
                }
            }

            float* Ob = gp + (isQ ? GP_Q2 : GP_P2);
            ull bp[4];
            if (!isQ) {
                const ulonglong2 bA = *reinterpret_cast<const ulonglong2*>(sm + OFF_B2 + j0);
                const ulonglong2 bB = *reinterpret_cast<const ulonglong2*>(sm + OFF_B2 + j0 + 4);
                bp[0] = bA.x; bp[1] = bA.y; bp[2] = bB.x; bp[3] = bB.y;
            } else {
                bp[0] = bp[1] = bp[2] = bp[3] = 0ULL;
            }
#pragma unroll
            for (int r = 0; r < 4; r++) {
                const int row = rg + r * 8;
                ulonglong2 s0, s1;
                s0.x = add2(acc[r][0], bp[0]); s0.y = add2(acc[r][1], bp[1]);
                s1.x = add2(acc[r][2], bp[2]); s1.y = add2(acc[r][3], bp[3]);
                *reinterpret_cast<ulonglong2*>(Ob + row * S2 + j0)     = s0;
                *reinterpret_cast<ulonglong2*>(Ob + row * S2 + j0 + 4) = s1;
            }
        }
        group_bar(gid);

        // ---- edge phase 2 (chunked channels) + fused pooling ----
        {
            const int i = ltid >> 3, s = ltid & 7;
            float acc[16];
            edge_phase_fast<4, S2>(gp + GP_P2, gp + GP_Q2, gp + GP_XS, idxs,
                                   sm + OFF_G2, sm + OFF_BE2,
                                   1.f / 128.f, i, s, gid, npass2, acc);
#pragma unroll
            for (int c = 0; c < 16; c++) {
                acc[c] += __shfl_xor_sync(0xffffffffu, acc[c], 8);
                acc[c] += __shfl_xor_sync(0xffffffffu, acc[c], 16);
            }
            float* wb = gp + GP_FB;            // warpbuf[8][128]
            const int w = ltid >> 5;
            if ((ltid & 24) == 0) {
#pragma unroll
                for (int j = 0; j < 4; j++)
                    *reinterpret_cast<float4*>(wb + w * 128 + s * 4 + j * 32) =
                        *reinterpret_cast<float4*>(acc + j * 4);
            }
        }
        group_bar(gid);

        // ---- final pool: mean over 32 points -> g_pool[cloud][128] ----
        if (ltid < 128) {
            const float* wb = gp + GP_FB;
            float s = 0.f;
#pragma unroll
            for (int w = 0; w < 8; w++) s += wb[w * 128 + ltid];
            g_pool[cloud * C2 + ltid] = s * (1.f / 32.f);
        }
    }
}

// out[4096,384] = g_pool[4096,128] @ Wo[128,384] + bo  (FFMA2, vectorized a)
__global__ __launch_bounds__(256)
void proj_kernel(const float* __restrict__ Wo, const float* __restrict__ bo,
                 float* __restrict__ out)
{
    extern __shared__ float sm2[];
    float* As = sm2;
    float* Ws = sm2 + 64 * 128;
    const int tid = threadIdx.x;
    const int row0 = blockIdx.x * 64;
    const int colB = blockIdx.y * 64;

    {
        const float4* ag = reinterpret_cast<const float4*>(g_pool + row0 * 128);
        float4* ad = reinterpret_cast<float4*>(As);
#pragma unroll
        for (int r = 0; r < 8; r++) ad[tid + r * 256] = ag[tid + r * 256];
    }
    for (int t = tid; t < 128 * 64; t += 256) {
        const int c = t >> 6, j = t & 63;
        Ws[t] = Wo[c * ECH + colB + j];
    }
    __syncthreads();

    const int r0 = (tid >> 4) * 4;
    const int c0 = (tid & 15) * 4;
    ull acc[4][2];
#pragma unroll
    for (int r = 0; r < 4; r++) { acc[r][0] = 0ULL; acc[r][1] = 0ULL; }

#pragma unroll 8
    for (int cb = 0; cb < 128; cb += 4) {
        float a4[4][4];
#pragma unroll
        for (int r = 0; r < 4; r++)
            *reinterpret_cast<float4*>(a4[r]) =
                *reinterpret_cast<const float4*>(As + (r0 + r) * 128 + cb);
#pragma unroll
        for (int cc = 0; cc < 4; cc++) {
            const ulonglong2 w = *reinterpret_cast<const ulonglong2*>(Ws + (cb + cc) * 64 + c0);
#pragma unroll
            for (int r = 0; r < 4; r++) {
                const ull aa = pk2(a4[r][cc], a4[r][cc]);
                acc[r][0] = fma2(aa, w.x, acc[r][0]);
                acc[r][1] = fma2(aa, w.y, acc[r][1]);
            }
        }
    }

    const ulonglong2 bb = *reinterpret_cast<const ulonglong2*>(bo + colB + c0);
#pragma unroll
    for (int r = 0; r < 4; r++) {
        ulonglong2 o;
        o.x = add2(acc[r][0], bb.x);
        o.y = add2(acc[r][1], bb.y);
        *reinterpret_cast<ulonglong2*>(out + (row0 + r0 + r) * ECH + colB + c0) = o;
    }
}

extern "C" void kernel_launch(void* const* d_in, const int* in_sizes, int n_in,
                              void* d_out, int out_size)
{
    const float* x   = (const float*)d_in[0];
    const float* W1  = (const float*)d_in[1];
    const float* b1  = (const float*)d_in[2];
    const float* g1  = (const float*)d_in[3];
    const float* be1 = (const float*)d_in[4];
    const float* W2  = (const float*)d_in[5];
    const float* b2  = (const float*)d_in[6];
    const float* g2  = (const float*)d_in[7];
    const float* be2 = (const float*)d_in[8];
    const float* Wo  = (const float*)d_in[9];
    const float* bo  = (const float*)d_in[10];
    float* out = (float*)d_out;

    cudaFuncSetAttribute(knn_encoder_kernel,
                         cudaFuncAttributeMaxDynamicSharedMemorySize, SMEM1_BYTES);
    cudaFuncSetAttribute(proj_kernel,
                         cudaFuncAttributeMaxDynamicSharedMemorySize, SMEM2_BYTES);

    knn_encoder_kernel<<<(NC + NGRP - 1) / NGRP, NTH, SMEM1_BYTES>>>(
        x, W1, b1, g1, be1, W2, b2, g2, be2);
    proj_kernel<<<dim3(NC / 64, ECH / 64), 256, SMEM2_BYTES>>>(Wo, bo, out);
}